// round 1
// baseline (speedup 1.0000x reference)
#include <cuda_runtime.h>

// Problem shape (fixed by setup_inputs)
#define NB   2
#define HIMG 48
#define WIMG 48
#define HW   2304        // 48*48
#define DM   768
#define NH   12
#define DH   64
#define QKVF 2304        // 3*DM
#define MROWS 4608       // NB*HW

// Scratch (device globals: allocation-free rule)
__device__ float g_qkv[(size_t)MROWS * QKVF];   // [b*HW + i][3*DM]
__device__ float g_o[(size_t)MROWS * DM];       // [b*HW + i][DM]

// ---------------------------------------------------------------------------
// SGEMM (NT): C[m,n] = sum_k A[m,k] * B[n,k]
// A: [M,K] row-major, B: [N,K] row-major, C: [M,N] row-major.
// BM=BN=128, BK=8, 256 threads, 8x8 per thread (split 4+4 tiles).
// Requires M%128==0, N%128==0, K%8==0 (true for all our calls).
// ---------------------------------------------------------------------------
__global__ void __launch_bounds__(256, 2) sgemm_nt(
    const float* __restrict__ A, const float* __restrict__ B,
    float* __restrict__ C, int M, int N, int K)
{
    __shared__ float As[8][128];
    __shared__ float Bs[8][128];

    const int tid = threadIdx.x;
    const int bm = blockIdx.y * 128;
    const int bn = blockIdx.x * 128;

    const int lrow = tid >> 1;            // 0..127
    const int lcol = (tid & 1) << 2;      // 0 or 4

    const float* Ap = A + (size_t)(bm + lrow) * K + lcol;
    const float* Bp = B + (size_t)(bn + lrow) * K + lcol;

    const int tx = tid & 15;              // 0..15
    const int ty = tid >> 4;              // 0..15
    const int row0 = ty * 4;              // rows row0..+4 and row0+64..+4
    const int col0 = tx * 4;

    float acc[8][8];
#pragma unroll
    for (int i = 0; i < 8; i++)
#pragma unroll
        for (int j = 0; j < 8; j++) acc[i][j] = 0.f;

    for (int k0 = 0; k0 < K; k0 += 8) {
        float4 av = *(const float4*)Ap;
        float4 bv = *(const float4*)Bp;
        As[lcol + 0][lrow] = av.x;
        As[lcol + 1][lrow] = av.y;
        As[lcol + 2][lrow] = av.z;
        As[lcol + 3][lrow] = av.w;
        Bs[lcol + 0][lrow] = bv.x;
        Bs[lcol + 1][lrow] = bv.y;
        Bs[lcol + 2][lrow] = bv.z;
        Bs[lcol + 3][lrow] = bv.w;
        __syncthreads();

#pragma unroll
        for (int k = 0; k < 8; k++) {
            float4 a0 = *(const float4*)&As[k][row0];
            float4 a1 = *(const float4*)&As[k][row0 + 64];
            float4 b0 = *(const float4*)&Bs[k][col0];
            float4 b1 = *(const float4*)&Bs[k][col0 + 64];
            float a[8] = {a0.x, a0.y, a0.z, a0.w, a1.x, a1.y, a1.z, a1.w};
            float b[8] = {b0.x, b0.y, b0.z, b0.w, b1.x, b1.y, b1.z, b1.w};
#pragma unroll
            for (int i = 0; i < 8; i++)
#pragma unroll
                for (int j = 0; j < 8; j++) acc[i][j] += a[i] * b[j];
        }
        __syncthreads();
        Ap += 8;
        Bp += 8;
    }

#pragma unroll
    for (int i = 0; i < 8; i++) {
        int r = bm + ((i < 4) ? (row0 + i) : (row0 + 64 + i - 4));
        float4 v0 = make_float4(acc[i][0], acc[i][1], acc[i][2], acc[i][3]);
        float4 v1 = make_float4(acc[i][4], acc[i][5], acc[i][6], acc[i][7]);
        *(float4*)&C[(size_t)r * N + bn + col0] = v0;
        *(float4*)&C[(size_t)r * N + bn + col0 + 64] = v1;
    }
}

// ---------------------------------------------------------------------------
// Neighborhood attention. One block per (qx image row, head, batch).
// 48 queries/block; K/V streamed one key-row (48 keys) at a time.
// 192 threads: softmax/PV mapping (qi = tid/4, part = tid%4 -> 16 dims),
// score mapping (qg = tid/16 -> 4 queries, kg = tid%16 -> 3 keys).
// Online softmax, fp32 throughout.
// ---------------------------------------------------------------------------
__global__ void __launch_bounds__(192) natten_attn(
    const float* __restrict__ qkv, const int* __restrict__ ks_ptr,
    float* __restrict__ o)
{
    const int qx = blockIdx.x;   // 0..47
    const int h  = blockIdx.y;   // 0..11
    const int b  = blockIdx.z;   // 0..1
    const int ksz = ks_ptr[0];   // 7

    __shared__ float Qs[48][64];
    __shared__ float Ks[48][65];     // pad 65: conflict-free strided reads
    __shared__ float Vs[48][64];
    __shared__ float Sm[48][49];
    __shared__ float row_rescale[48];
    __shared__ float row_l[48];

    const int tid = threadIdx.x;

    // Load Q tile: queries i = qx*48 + r
    const float* qbase = qkv + ((size_t)b * HW + (size_t)qx * 48) * QKVF + h * DH;
    for (int idx = tid; idx < 48 * 16; idx += 192) {
        int r = idx >> 4, c4 = (idx & 15) << 2;
        *(float4*)&Qs[r][c4] = *(const float4*)(qbase + (size_t)r * QKVF + c4);
    }

    const int qi   = tid >> 2;       // 0..47
    const int part = tid & 3;        // 0..3
    const int d0   = part * 16;
    const int qg   = tid >> 4;       // 0..11
    const int kg   = tid & 15;       // 0..15

    float accv[16];
#pragma unroll
    for (int i = 0; i < 16; i++) accv[i] = 0.f;
    float m_run = -1e30f;
    float l_run = 0.f;

    const int jlo = max(0, qi - ksz);
    const int jhi = min(47, qi + ksz);

    const int kr_lo = max(0, qx - ksz);
    const int kr_hi = min(47, qx + ksz);

    for (int kr = kr_lo; kr <= kr_hi; kr++) {
        __syncthreads();  // prior PV readers done before K/V overwrite
        const float* kbase = qkv + ((size_t)b * HW + (size_t)kr * 48) * QKVF + DM + h * DH;
        const float* vbase = kbase + DM;
        for (int idx = tid; idx < 48 * 16; idx += 192) {
            int r = idx >> 4, c4 = (idx & 15) << 2;
            float4 kv = *(const float4*)(kbase + (size_t)r * QKVF + c4);
            Ks[r][c4 + 0] = kv.x;
            Ks[r][c4 + 1] = kv.y;
            Ks[r][c4 + 2] = kv.z;
            Ks[r][c4 + 3] = kv.w;
            *(float4*)&Vs[r][c4] = *(const float4*)(vbase + (size_t)r * QKVF + c4);
        }
        __syncthreads();

        // ---- scores: thread tile 4 queries x 3 keys ----
        float s[4][3];
#pragma unroll
        for (int a = 0; a < 4; a++)
#pragma unroll
            for (int c = 0; c < 3; c++) s[a][c] = 0.f;

        const int qlo_t = qg * 4, qhi_t = qg * 4 + 3;
        const int klo_t = kg * 3, khi_t = kg * 3 + 2;
        // any pair in this tile unmasked?
        const bool any_valid = (klo_t - qhi_t <= ksz) && (qlo_t - khi_t <= ksz);
        if (any_valid) {
#pragma unroll 8
            for (int d = 0; d < 64; d++) {
                float a0 = Qs[qlo_t + 0][d];
                float a1 = Qs[qlo_t + 1][d];
                float a2 = Qs[qlo_t + 2][d];
                float a3 = Qs[qlo_t + 3][d];
                float b0 = Ks[klo_t + 0][d];
                float b1 = Ks[klo_t + 1][d];
                float b2 = Ks[klo_t + 2][d];
                s[0][0] += a0 * b0; s[0][1] += a0 * b1; s[0][2] += a0 * b2;
                s[1][0] += a1 * b0; s[1][1] += a1 * b1; s[1][2] += a1 * b2;
                s[2][0] += a2 * b0; s[2][1] += a2 * b1; s[2][2] += a2 * b2;
                s[3][0] += a3 * b0; s[3][1] += a3 * b1; s[3][2] += a3 * b2;
            }
        }
#pragma unroll
        for (int a = 0; a < 4; a++)
#pragma unroll
            for (int c = 0; c < 3; c++) {
                int qy = qlo_t + a, ky = klo_t + c;
                int dd = (qy > ky) ? (qy - ky) : (ky - qy);
                Sm[qy][ky] = (dd <= ksz) ? s[a][c] * 0.125f : -1e30f;
            }
        __syncthreads();

        // ---- online softmax (one thread per query row) ----
        if (part == 0) {
            float mt = -1e30f;
            for (int j = jlo; j <= jhi; j++) mt = fmaxf(mt, Sm[qi][j]);
            float m_new = fmaxf(m_run, mt);
            float rsc = __expf(m_run - m_new);
            float sum = 0.f;
            for (int j = jlo; j <= jhi; j++) {
                float p = __expf(Sm[qi][j] - m_new);
                Sm[qi][j] = p;
                sum += p;
            }
            l_run = l_run * rsc + sum;
            m_run = m_new;
            row_rescale[qi] = rsc;
            row_l[qi] = l_run;
        }
        __syncthreads();

        // ---- PV accumulate (restricted to valid column window) ----
        float rsc = row_rescale[qi];
#pragma unroll
        for (int i = 0; i < 16; i++) accv[i] *= rsc;
        for (int kj = jlo; kj <= jhi; kj++) {
            float p = Sm[qi][kj];
            float4 v0 = *(const float4*)&Vs[kj][d0 + 0];
            float4 v1 = *(const float4*)&Vs[kj][d0 + 4];
            float4 v2 = *(const float4*)&Vs[kj][d0 + 8];
            float4 v3 = *(const float4*)&Vs[kj][d0 + 12];
            accv[0]  += p * v0.x; accv[1]  += p * v0.y;
            accv[2]  += p * v0.z; accv[3]  += p * v0.w;
            accv[4]  += p * v1.x; accv[5]  += p * v1.y;
            accv[6]  += p * v1.z; accv[7]  += p * v1.w;
            accv[8]  += p * v2.x; accv[9]  += p * v2.y;
            accv[10] += p * v2.z; accv[11] += p * v2.w;
            accv[12] += p * v3.x; accv[13] += p * v3.y;
            accv[14] += p * v3.z; accv[15] += p * v3.w;
        }
    }

    // finalize
    float inv_l = 1.f / row_l[qi];
    float* obase = o + ((size_t)b * HW + (size_t)qx * 48 + qi) * DM + h * DH + d0;
    float4 w0 = make_float4(accv[0] * inv_l, accv[1] * inv_l, accv[2] * inv_l, accv[3] * inv_l);
    float4 w1 = make_float4(accv[4] * inv_l, accv[5] * inv_l, accv[6] * inv_l, accv[7] * inv_l);
    float4 w2 = make_float4(accv[8] * inv_l, accv[9] * inv_l, accv[10] * inv_l, accv[11] * inv_l);
    float4 w3 = make_float4(accv[12] * inv_l, accv[13] * inv_l, accv[14] * inv_l, accv[15] * inv_l);
    *(float4*)(obase + 0)  = w0;
    *(float4*)(obase + 4)  = w1;
    *(float4*)(obase + 8)  = w2;
    *(float4*)(obase + 12) = w3;
}

// ---------------------------------------------------------------------------
extern "C" void kernel_launch(void* const* d_in, const int* in_sizes, int n_in,
                              void* d_out, int out_size)
{
    const float* x     = (const float*)d_in[0];  // [2,48,48,768]
    const float* w_qkv = (const float*)d_in[1];  // [2304,768]
    const float* w_out = (const float*)d_in[2];  // [768,768]
    const int*   ksz   = (const int*)d_in[3];    // scalar 7
    float* out = (float*)d_out;                  // [2,48,48,768]

    float* qkv_buf;
    float* o_buf;
    cudaGetSymbolAddress((void**)&qkv_buf, g_qkv);
    cudaGetSymbolAddress((void**)&o_buf, g_o);

    // QKV projection: [4608,768] x [2304,768]^T -> [4608,2304]
    dim3 g1(QKVF / 128, MROWS / 128);
    sgemm_nt<<<g1, 256>>>(x, w_qkv, qkv_buf, MROWS, QKVF, DM);

    // Neighborhood attention -> o_buf [4608,768]
    dim3 g2(HIMG, NH, NB);
    natten_attn<<<g2, 192>>>(qkv_buf, ksz, o_buf);

    // Output projection: [4608,768] x [768,768]^T -> [4608,768]
    dim3 g3(DM / 128, MROWS / 128);
    sgemm_nt<<<g3, 256>>>(o_buf, w_out, out, MROWS, DM, DM);
}

// round 4
// speedup vs baseline: 1.5417x; 1.5417x over previous
#include <cuda_runtime.h>
#include <cstdint>

// Problem shape (fixed by setup_inputs)
#define NB   2
#define HIMG 48
#define WIMG 48
#define HW   2304        // 48*48
#define DM   768
#define NH   12
#define DH   64
#define QKVF 2304        // 3*DM
#define MROWS 4608       // NB*HW

// Scratch (device globals: allocation-free rule)
__device__ float g_qkv[(size_t)MROWS * QKVF];   // [b*HW + i][3*DM]
__device__ float g_o[(size_t)MROWS * DM];       // [b*HW + i][DM]

// ---------------------------------------------------------------------------
// tf32 helpers (legacy mma.sync path — works with .target sm_100)
// ---------------------------------------------------------------------------
__device__ __forceinline__ uint32_t f2tf32(float x) {
    uint32_t u;
    asm("cvt.rna.tf32.f32 %0, %1;" : "=r"(u) : "f"(x));
    return u;
}

#define MMA_TF32_16x8x8(d, a, b) \
    asm volatile("mma.sync.aligned.m16n8k8.row.col.f32.tf32.tf32.f32 " \
        "{%0,%1,%2,%3}, {%4,%5,%6,%7}, {%8,%9}, {%0,%1,%2,%3};" \
        : "+f"((d)[0]), "+f"((d)[1]), "+f"((d)[2]), "+f"((d)[3]) \
        : "r"((a)[0]), "r"((a)[1]), "r"((a)[2]), "r"((a)[3]), \
          "r"((b)[0]), "r"((b)[1]))

// ============================================================================
// TF32 tensor-core GEMM (NT): C[m,n] = sum_k A[m,k] * B[n,k]
// A: [M,K] row-major, B: [N,K] row-major, C: [M,N] row-major.
// CTA tile 128x128, K-chunk 32. 256 threads = 8 warps (2x4), warp tile 64x32
// = 4x4 grid of m16n8k8 MMA tiles. Requires M%128==0, N%128==0, K%32==0.
// ============================================================================
#define SSTRIDE 36   // smem row stride in floats (bank-spread for fragments)

__global__ void __launch_bounds__(256, 2) tf32_mma_gemm_nt(
    const float* __restrict__ A, const float* __restrict__ B,
    float* __restrict__ C, int M, int N, int K)
{
    __shared__ float As[128][SSTRIDE];
    __shared__ float Bs[128][SSTRIDE];

    const int tid  = threadIdx.x;
    const int lane = tid & 31;
    const int wid  = tid >> 5;
    const int warp_m = wid >> 2;     // 0..1
    const int warp_n = wid & 3;      // 0..3

    const int bm = blockIdx.y * 128;
    const int bn = blockIdx.x * 128;

    const int g = lane >> 2;         // 0..7  (row within MMA tile)
    const int t = lane & 3;          // 0..3  (k / col-pair index)
    const int m0 = warp_m * 64;
    const int n0 = warp_n * 32;

    float acc[4][4][4];
#pragma unroll
    for (int mt = 0; mt < 4; mt++)
#pragma unroll
        for (int nt = 0; nt < 4; nt++)
#pragma unroll
            for (int i = 0; i < 4; i++) acc[mt][nt][i] = 0.f;

    const int ldrow = tid >> 3;          // 0..31
    const int ldcol = (tid & 7) * 4;     // 0,4,...,28

    const int NC = K / 32;
    for (int c = 0; c < NC; c++) {
        __syncthreads();   // previous chunk's MMA reads done
#pragma unroll
        for (int i = 0; i < 4; i++) {
            int row = ldrow + i * 32;
            const float* Ap = A + (size_t)(bm + row) * K + c * 32 + ldcol;
            const float* Bp = B + (size_t)(bn + row) * K + c * 32 + ldcol;
            float4 a = *(const float4*)Ap;
            float4 b = *(const float4*)Bp;
            uint4 au = make_uint4(f2tf32(a.x), f2tf32(a.y), f2tf32(a.z), f2tf32(a.w));
            uint4 bu = make_uint4(f2tf32(b.x), f2tf32(b.y), f2tf32(b.z), f2tf32(b.w));
            *(uint4*)&As[row][ldcol] = au;
            *(uint4*)&Bs[row][ldcol] = bu;
        }
        __syncthreads();

#pragma unroll
        for (int kk = 0; kk < 32; kk += 8) {
            uint32_t af[4][4];
            uint32_t bf[4][2];
#pragma unroll
            for (int mt = 0; mt < 4; mt++) {
                int r = m0 + mt * 16 + g;
                af[mt][0] = __float_as_uint(As[r][kk + t]);
                af[mt][1] = __float_as_uint(As[r + 8][kk + t]);
                af[mt][2] = __float_as_uint(As[r][kk + t + 4]);
                af[mt][3] = __float_as_uint(As[r + 8][kk + t + 4]);
            }
#pragma unroll
            for (int nt = 0; nt < 4; nt++) {
                int nr = n0 + nt * 8 + g;
                bf[nt][0] = __float_as_uint(Bs[nr][kk + t]);
                bf[nt][1] = __float_as_uint(Bs[nr][kk + t + 4]);
            }
#pragma unroll
            for (int mt = 0; mt < 4; mt++)
#pragma unroll
                for (int nt = 0; nt < 4; nt++)
                    MMA_TF32_16x8x8(acc[mt][nt], af[mt], bf[nt]);
        }
    }

    // Epilogue: c0,c1 -> (row, 2t..2t+1), c2,c3 -> (row+8, 2t..2t+1)
#pragma unroll
    for (int mt = 0; mt < 4; mt++) {
#pragma unroll
        for (int nt = 0; nt < 4; nt++) {
            int r  = bm + m0 + mt * 16 + g;
            int cc = bn + n0 + nt * 8 + t * 2;
            float2 v0 = make_float2(acc[mt][nt][0], acc[mt][nt][1]);
            float2 v1 = make_float2(acc[mt][nt][2], acc[mt][nt][3]);
            *(float2*)&C[(size_t)r * N + cc] = v0;
            *(float2*)&C[(size_t)(r + 8) * N + cc] = v1;
        }
    }
}

// ---------------------------------------------------------------------------
// Neighborhood attention (unchanged, passing in R1).
// One block per (qx image row, head, batch); online softmax, fp32.
// ---------------------------------------------------------------------------
__global__ void __launch_bounds__(192) natten_attn(
    const float* __restrict__ qkv, const int* __restrict__ ks_ptr,
    float* __restrict__ o)
{
    const int qx = blockIdx.x;
    const int h  = blockIdx.y;
    const int b  = blockIdx.z;
    const int ksz = ks_ptr[0];

    __shared__ float Qs[48][64];
    __shared__ float Ks[48][65];
    __shared__ float Vs[48][64];
    __shared__ float Sm[48][49];
    __shared__ float row_rescale[48];
    __shared__ float row_l[48];

    const int tid = threadIdx.x;

    const float* qbase = qkv + ((size_t)b * HW + (size_t)qx * 48) * QKVF + h * DH;
    for (int idx = tid; idx < 48 * 16; idx += 192) {
        int r = idx >> 4, c4 = (idx & 15) << 2;
        *(float4*)&Qs[r][c4] = *(const float4*)(qbase + (size_t)r * QKVF + c4);
    }

    const int qi   = tid >> 2;
    const int part = tid & 3;
    const int d0   = part * 16;
    const int qg   = tid >> 4;
    const int kg   = tid & 15;

    float accv[16];
#pragma unroll
    for (int i = 0; i < 16; i++) accv[i] = 0.f;
    float m_run = -1e30f;
    float l_run = 0.f;

    const int jlo = max(0, qi - ksz);
    const int jhi = min(47, qi + ksz);
    const int kr_lo = max(0, qx - ksz);
    const int kr_hi = min(47, qx + ksz);

    for (int kr = kr_lo; kr <= kr_hi; kr++) {
        __syncthreads();
        const float* kbase = qkv + ((size_t)b * HW + (size_t)kr * 48) * QKVF + DM + h * DH;
        const float* vbase = kbase + DM;
        for (int idx = tid; idx < 48 * 16; idx += 192) {
            int r = idx >> 4, c4 = (idx & 15) << 2;
            float4 kv = *(const float4*)(kbase + (size_t)r * QKVF + c4);
            Ks[r][c4 + 0] = kv.x;
            Ks[r][c4 + 1] = kv.y;
            Ks[r][c4 + 2] = kv.z;
            Ks[r][c4 + 3] = kv.w;
            *(float4*)&Vs[r][c4] = *(const float4*)(vbase + (size_t)r * QKVF + c4);
        }
        __syncthreads();

        float s[4][3];
#pragma unroll
        for (int a = 0; a < 4; a++)
#pragma unroll
            for (int c = 0; c < 3; c++) s[a][c] = 0.f;

        const int qlo_t = qg * 4, qhi_t = qg * 4 + 3;
        const int klo_t = kg * 3, khi_t = kg * 3 + 2;
        const bool any_valid = (klo_t - qhi_t <= ksz) && (qlo_t - khi_t <= ksz);
        if (any_valid) {
#pragma unroll 8
            for (int d = 0; d < 64; d++) {
                float a0 = Qs[qlo_t + 0][d];
                float a1 = Qs[qlo_t + 1][d];
                float a2 = Qs[qlo_t + 2][d];
                float a3 = Qs[qlo_t + 3][d];
                float b0 = Ks[klo_t + 0][d];
                float b1 = Ks[klo_t + 1][d];
                float b2 = Ks[klo_t + 2][d];
                s[0][0] += a0 * b0; s[0][1] += a0 * b1; s[0][2] += a0 * b2;
                s[1][0] += a1 * b0; s[1][1] += a1 * b1; s[1][2] += a1 * b2;
                s[2][0] += a2 * b0; s[2][1] += a2 * b1; s[2][2] += a2 * b2;
                s[3][0] += a3 * b0; s[3][1] += a3 * b1; s[3][2] += a3 * b2;
            }
        }
#pragma unroll
        for (int a = 0; a < 4; a++)
#pragma unroll
            for (int c = 0; c < 3; c++) {
                int qy = qlo_t + a, ky = klo_t + c;
                int dd = (qy > ky) ? (qy - ky) : (ky - qy);
                Sm[qy][ky] = (dd <= ksz) ? s[a][c] * 0.125f : -1e30f;
            }
        __syncthreads();

        if (part == 0) {
            float mt = -1e30f;
            for (int j = jlo; j <= jhi; j++) mt = fmaxf(mt, Sm[qi][j]);
            float m_new = fmaxf(m_run, mt);
            float rsc = __expf(m_run - m_new);
            float sum = 0.f;
            for (int j = jlo; j <= jhi; j++) {
                float p = __expf(Sm[qi][j] - m_new);
                Sm[qi][j] = p;
                sum += p;
            }
            l_run = l_run * rsc + sum;
            m_run = m_new;
            row_rescale[qi] = rsc;
            row_l[qi] = l_run;
        }
        __syncthreads();

        float rsc = row_rescale[qi];
#pragma unroll
        for (int i = 0; i < 16; i++) accv[i] *= rsc;
        for (int kj = jlo; kj <= jhi; kj++) {
            float p = Sm[qi][kj];
            float4 v0 = *(const float4*)&Vs[kj][d0 + 0];
            float4 v1 = *(const float4*)&Vs[kj][d0 + 4];
            float4 v2 = *(const float4*)&Vs[kj][d0 + 8];
            float4 v3 = *(const float4*)&Vs[kj][d0 + 12];
            accv[0]  += p * v0.x; accv[1]  += p * v0.y;
            accv[2]  += p * v0.z; accv[3]  += p * v0.w;
            accv[4]  += p * v1.x; accv[5]  += p * v1.y;
            accv[6]  += p * v1.z; accv[7]  += p * v1.w;
            accv[8]  += p * v2.x; accv[9]  += p * v2.y;
            accv[10] += p * v2.z; accv[11] += p * v2.w;
            accv[12] += p * v3.x; accv[13] += p * v3.y;
            accv[14] += p * v3.z; accv[15] += p * v3.w;
        }
    }

    float inv_l = 1.f / row_l[qi];
    float* obase = o + ((size_t)b * HW + (size_t)qx * 48 + qi) * DM + h * DH + d0;
    float4 w0 = make_float4(accv[0] * inv_l, accv[1] * inv_l, accv[2] * inv_l, accv[3] * inv_l);
    float4 w1 = make_float4(accv[4] * inv_l, accv[5] * inv_l, accv[6] * inv_l, accv[7] * inv_l);
    float4 w2 = make_float4(accv[8] * inv_l, accv[9] * inv_l, accv[10] * inv_l, accv[11] * inv_l);
    float4 w3 = make_float4(accv[12] * inv_l, accv[13] * inv_l, accv[14] * inv_l, accv[15] * inv_l);
    *(float4*)(obase + 0)  = w0;
    *(float4*)(obase + 4)  = w1;
    *(float4*)(obase + 8)  = w2;
    *(float4*)(obase + 12) = w3;
}

// ---------------------------------------------------------------------------
extern "C" void kernel_launch(void* const* d_in, const int* in_sizes, int n_in,
                              void* d_out, int out_size)
{
    const float* x     = (const float*)d_in[0];  // [2,48,48,768]
    const float* w_qkv = (const float*)d_in[1];  // [2304,768]
    const float* w_out = (const float*)d_in[2];  // [768,768]
    const int*   ksz   = (const int*)d_in[3];    // scalar 7
    float* out = (float*)d_out;                  // [2,48,48,768]

    float* qkv_buf;
    float* o_buf;
    cudaGetSymbolAddress((void**)&qkv_buf, g_qkv);
    cudaGetSymbolAddress((void**)&o_buf, g_o);

    // QKV projection: [4608,768] x [2304,768]^T -> [4608,2304]
    dim3 g1(QKVF / 128, MROWS / 128);
    tf32_mma_gemm_nt<<<g1, 256>>>(x, w_qkv, qkv_buf, MROWS, QKVF, DM);

    // Neighborhood attention -> o_buf [4608,768]
    dim3 g2(HIMG, NH, NB);
    natten_attn<<<g2, 192>>>(qkv_buf, ksz, o_buf);

    // Output projection: [4608,768] x [768,768]^T -> [4608,768]
    dim3 g3(DM / 128, MROWS / 128);
    tf32_mma_gemm_nt<<<g3, 256>>>(o_buf, w_out, out, MROWS, DM, DM);
}